// round 7
// baseline (speedup 1.0000x reference)
#include <cuda_runtime.h>
#include <cuda_bf16.h>
#include <cstdint>
#include <cstddef>

#define N_NODES 100000
#define M_PAD   100096            // 782 * 128
#define N_EDGES 3200000
#define DIM 512

// ---------------- scratch (device globals; no runtime allocation) ----------
__device__ float         g_bufA[(size_t)M_PAD * DIM];   // gemm1 output
__device__ float         g_bufC[(size_t)M_PAD * DIM];   // gemm2 output
__device__ __nv_bfloat16 g_xhi[(size_t)M_PAD * DIM];
__device__ __nv_bfloat16 g_xlo[(size_t)M_PAD * DIM];
__device__ __nv_bfloat16 g_h1hi[(size_t)M_PAD * DIM];   // pad rows stay zero-init
__device__ __nv_bfloat16 g_h1lo[(size_t)M_PAD * DIM];
__device__ __nv_bfloat16 g_w1thi[DIM * DIM];
__device__ __nv_bfloat16 g_w1tlo[DIM * DIM];
__device__ __nv_bfloat16 g_w2thi[DIM * DIM];
__device__ __nv_bfloat16 g_w2tlo[DIM * DIM];
__device__ int   g_row_ptr[N_NODES + 1];
__device__ int   g_counts[N_NODES];
__device__ int   g_srcs[N_EDGES];
__device__ float g_vals[N_EDGES];

// ---------------- PTX helpers ----------------------------------------------
__device__ __forceinline__ uint32_t smem_u32(const void* p) {
    uint32_t a;
    asm("{ .reg .u64 t; cvta.to.shared.u64 t, %1; cvt.u32.u64 %0, t; }" : "=r"(a) : "l"(p));
    return a;
}

#define CP_ASYNC16(smaddr, gptr) \
    asm volatile("cp.async.cg.shared.global [%0], [%1], 16;" :: "r"(smaddr), "l"(gptr))
#define CP_COMMIT() asm volatile("cp.async.commit_group;" ::: "memory")
#define CP_WAIT(N)  asm volatile("cp.async.wait_group %0;" :: "n"(N) : "memory")

#define LDSM4(R0, R1, R2, R3, addr) \
    asm volatile("ldmatrix.sync.aligned.m8n8.x4.shared.b16 {%0,%1,%2,%3}, [%4];" \
                 : "=r"(R0), "=r"(R1), "=r"(R2), "=r"(R3) : "r"(addr))

#define MMA16816(C, A, B0, B1) \
    asm volatile("mma.sync.aligned.m16n8k16.row.col.f32.bf16.bf16.f32 " \
                 "{%0,%1,%2,%3}, {%4,%5,%6,%7}, {%8,%9}, {%0,%1,%2,%3};" \
                 : "+f"((C)[0]), "+f"((C)[1]), "+f"((C)[2]), "+f"((C)[3]) \
                 : "r"((A)[0]), "r"((A)[1]), "r"((A)[2]), "r"((A)[3]), \
                   "r"(B0), "r"(B1))

// ---------------- CSR build -------------------------------------------------
__global__ void zero_counts_kernel() {
    int i = blockIdx.x * blockDim.x + threadIdx.x;
    if (i < N_NODES) g_counts[i] = 0;
}

__global__ void hist_kernel(const int* __restrict__ dst) {
    int e = blockIdx.x * blockDim.x + threadIdx.x;
    if (e < N_EDGES) atomicAdd(&g_counts[__ldcs(dst + e)], 1);
}

__global__ __launch_bounds__(1024) void scan_kernel() {
    __shared__ int partials[1024];
    int tid = threadIdx.x;
    const int CHUNK = (N_NODES + 1023) / 1024;
    int b = tid * CHUNK;
    int e = b + CHUNK; if (e > N_NODES) e = N_NODES;
    if (b > N_NODES) b = N_NODES;
    int sum = 0;
    for (int i = b; i < e; i++) sum += g_counts[i];
    partials[tid] = sum;
    __syncthreads();
    for (int off = 1; off < 1024; off <<= 1) {
        int t = (tid >= off) ? partials[tid - off] : 0;
        __syncthreads();
        partials[tid] += t;
        __syncthreads();
    }
    int run = partials[tid] - sum;
    for (int i = b; i < e; i++) {
        g_row_ptr[i] = run;
        run += g_counts[i];
        g_counts[i] = 0;
    }
    if (tid == 1023) g_row_ptr[N_NODES] = partials[1023];
}

__global__ void scatter_kernel(const int* __restrict__ src, const int* __restrict__ dst,
                               const float* __restrict__ val) {
    int e = blockIdx.x * blockDim.x + threadIdx.x;
    if (e >= N_EDGES) return;
    int d = __ldcs(dst + e);
    int pos = g_row_ptr[d] + atomicAdd(&g_counts[d], 1);
    g_srcs[pos] = __ldcs(src + e);
    g_vals[pos] = __ldcs(val + e);
}

// ---------------- input prep: bf16 hi/lo splits ------------------------------
__global__ void split_x_kernel(const float* __restrict__ x) {
    size_t i = (size_t)blockIdx.x * blockDim.x + threadIdx.x;  // float4 index
    const size_t total = (size_t)M_PAD * DIM / 4;
    if (i >= total) return;
    size_t row = i / (DIM / 4);
    float4 v = make_float4(0.f, 0.f, 0.f, 0.f);
    if (row < N_NODES) v = ((const float4*)x)[i];
    __nv_bfloat16 hx = __float2bfloat16(v.x), hy = __float2bfloat16(v.y);
    __nv_bfloat16 hz = __float2bfloat16(v.z), hw = __float2bfloat16(v.w);
    ushort4 h = make_ushort4(__bfloat16_as_ushort(hx), __bfloat16_as_ushort(hy),
                             __bfloat16_as_ushort(hz), __bfloat16_as_ushort(hw));
    __nv_bfloat16 lx = __float2bfloat16(v.x - __bfloat162float(hx));
    __nv_bfloat16 ly = __float2bfloat16(v.y - __bfloat162float(hy));
    __nv_bfloat16 lz = __float2bfloat16(v.z - __bfloat162float(hz));
    __nv_bfloat16 lw = __float2bfloat16(v.w - __bfloat162float(hw));
    ushort4 l = make_ushort4(__bfloat16_as_ushort(lx), __bfloat16_as_ushort(ly),
                             __bfloat16_as_ushort(lz), __bfloat16_as_ushort(lw));
    ((ushort4*)g_xhi)[i] = h;
    ((ushort4*)g_xlo)[i] = l;
}

// W[k][n] -> Wt[n][k], split hi/lo
__global__ void wsplit_kernel(const float* __restrict__ W,
                              __nv_bfloat16* __restrict__ hi, __nv_bfloat16* __restrict__ lo) {
    int idx = blockIdx.x * blockDim.x + threadIdx.x;
    if (idx >= DIM * DIM) return;
    int k = idx >> 9, n = idx & 511;
    float v = W[idx];
    __nv_bfloat16 h = __float2bfloat16(v);
    __nv_bfloat16 l = __float2bfloat16(v - __bfloat162float(h));
    hi[n * DIM + k] = h;
    lo[n * DIM + k] = l;
}

// ---------------- shared GEMM machinery (R4-proven) ---------------------------
#define BK 32
#define ROWB 80
#define OFF_AHI 0
#define OFF_ALO 10240
#define OFF_BHI 20480
#define OFF_BLO 30720
#define STAGE_BYTES 40960
#define GEMM_SMEM (2 * STAGE_BYTES)
#define NIT (DIM / BK)               // 16

__device__ __forceinline__ void stage_load(
    uint32_t sbase, int stage,
    const __nv_bfloat16* __restrict__ Ahi, const __nv_bfloat16* __restrict__ Alo,
    const __nv_bfloat16* __restrict__ Bhi, const __nv_bfloat16* __restrict__ Blo,
    int m0, int n0, int k0, int tid)
{
    uint32_t s0 = sbase + (uint32_t)stage * STAGE_BYTES;
#pragma unroll
    for (int i = tid; i < 512; i += 256) {
        int r = i >> 2, s = i & 3;
        uint32_t so = (uint32_t)r * ROWB + (uint32_t)s * 16u;
        const char* ga = (const char*)(Ahi + (size_t)(m0 + r) * DIM + k0) + s * 16;
        const char* gb = (const char*)(Alo + (size_t)(m0 + r) * DIM + k0) + s * 16;
        const char* gc = (const char*)(Bhi + (size_t)(n0 + r) * DIM + k0) + s * 16;
        const char* gd = (const char*)(Blo + (size_t)(n0 + r) * DIM + k0) + s * 16;
        CP_ASYNC16(s0 + OFF_AHI + so, ga);
        CP_ASYNC16(s0 + OFF_ALO + so, gb);
        CP_ASYNC16(s0 + OFF_BHI + so, gc);
        CP_ASYNC16(s0 + OFF_BLO + so, gd);
    }
}

// full 128x128 K-loop + epilogue; callable from standalone and fused kernels
__device__ __forceinline__ void gemm_block_128x128(
    uint32_t sbase,
    const __nv_bfloat16* __restrict__ Ahi, const __nv_bfloat16* __restrict__ Alo,
    const __nv_bfloat16* __restrict__ Bhi, const __nv_bfloat16* __restrict__ Blo,
    const float* __restrict__ bias, float* __restrict__ C,
    int m0, int n0, int tid)
{
    const int warp = tid >> 5;
    const int lane = tid & 31;
    const int wm = warp & 1;
    const int wn = warp >> 1;

    float acc[4][4][4];
#pragma unroll
    for (int a = 0; a < 4; a++)
#pragma unroll
        for (int b = 0; b < 4; b++)
#pragma unroll
            for (int c = 0; c < 4; c++) acc[a][b][c] = 0.f;

    const int a_row = lane & 15;
    const int a_koff = (lane >> 4) * 8;
    const int b_g = lane >> 3;
    const int b_nloc = ((b_g >> 1) << 3) + (lane & 7);
    const int b_koff = (b_g & 1) * 8;

    stage_load(sbase, 0, Ahi, Alo, Bhi, Blo, m0, n0, 0, tid);
    CP_COMMIT();

    for (int it = 0; it < NIT; ++it) {
        if (it + 1 < NIT) {
            stage_load(sbase, (it + 1) & 1, Ahi, Alo, Bhi, Blo, m0, n0, (it + 1) * BK, tid);
            CP_COMMIT();
            CP_WAIT(1);
        } else {
            CP_WAIT(0);
        }
        __syncthreads();

        const uint32_t st = sbase + (uint32_t)(it & 1) * STAGE_BYTES;
#pragma unroll
        for (int kk = 0; kk < 2; ++kk) {
            const int k16 = kk * 16;
            uint32_t ahi[4][4], alo[4][4];
#pragma unroll
            for (int mi = 0; mi < 4; ++mi) {
                uint32_t ra = (uint32_t)(wm * 64 + mi * 16 + a_row) * ROWB
                            + (uint32_t)(k16 + a_koff) * 2;
                LDSM4(ahi[mi][0], ahi[mi][1], ahi[mi][2], ahi[mi][3], st + OFF_AHI + ra);
                LDSM4(alo[mi][0], alo[mi][1], alo[mi][2], alo[mi][3], st + OFF_ALO + ra);
            }
            uint32_t bhi[2][4], blo[2][4];
#pragma unroll
            for (int nb = 0; nb < 2; ++nb) {
                uint32_t rb = (uint32_t)(wn * 32 + nb * 16 + b_nloc) * ROWB
                            + (uint32_t)(k16 + b_koff) * 2;
                LDSM4(bhi[nb][0], bhi[nb][1], bhi[nb][2], bhi[nb][3], st + OFF_BHI + rb);
                LDSM4(blo[nb][0], blo[nb][1], blo[nb][2], blo[nb][3], st + OFF_BLO + rb);
            }
#pragma unroll
            for (int mi = 0; mi < 4; ++mi) {
#pragma unroll
                for (int j = 0; j < 4; ++j) {
                    const int nb = j >> 1, blk = j & 1;
                    MMA16816(acc[mi][j], ahi[mi], bhi[nb][blk * 2], bhi[nb][blk * 2 + 1]);
                    MMA16816(acc[mi][j], ahi[mi], blo[nb][blk * 2], blo[nb][blk * 2 + 1]);
                    MMA16816(acc[mi][j], alo[mi], bhi[nb][blk * 2], bhi[nb][blk * 2 + 1]);
                }
            }
        }
        __syncthreads();
    }

    // epilogue: bias add + plain fp32 store (keep in L2 for consumer)
#pragma unroll
    for (int mi = 0; mi < 4; ++mi) {
        int row = m0 + wm * 64 + mi * 16 + (lane >> 2);
#pragma unroll
        for (int j = 0; j < 4; ++j) {
            int col = n0 + wn * 32 + j * 8 + (lane & 3) * 2;
            float b0 = bias[col], b1 = bias[col + 1];
            float2 v0 = make_float2(acc[mi][j][0] + b0, acc[mi][j][1] + b1);
            float2 v1 = make_float2(acc[mi][j][2] + b0, acc[mi][j][3] + b1);
            *(float2*)(C + (size_t)row * DIM + col) = v0;
            *(float2*)(C + (size_t)(row + 8) * DIM + col) = v1;
        }
    }
}

__global__ __launch_bounds__(256, 2) void gemm_mma_kernel(
    const __nv_bfloat16* __restrict__ Ahi, const __nv_bfloat16* __restrict__ Alo,
    const __nv_bfloat16* __restrict__ Bhi, const __nv_bfloat16* __restrict__ Blo,
    const float* __restrict__ bias, float* __restrict__ C)
{
    extern __shared__ char sm[];
    const uint32_t sbase = smem_u32(sm);
    // n fastest -> each wave shares the same A rows across 4 n-blocks
    const int n0 = blockIdx.x * 128;
    const int m0 = blockIdx.y * 128;
    gemm_block_128x128(sbase, Ahi, Alo, Bhi, Blo, bias, C, m0, n0, threadIdx.x);
}

// ---------------- SpMM pieces ------------------------------------------------
__device__ __forceinline__ void fma4(float4& acc, float v, const float4& a) {
    acc.x += v * a.x; acc.y += v * a.y; acc.z += v * a.z; acc.w += v * a.w;
}
__device__ __forceinline__ float4 relu4(float4 a) {
    a.x = fmaxf(a.x, 0.f); a.y = fmaxf(a.y, 0.f);
    a.z = fmaxf(a.z, 0.f); a.w = fmaxf(a.w, 0.f);
    return a;
}

__device__ __forceinline__ void gather_row(const float* __restrict__ H, int beg, int end,
                                           int lane, float4& a0, float4& a1, float4& a2, float4& a3) {
    for (int base = beg; base < end; base += 32) {
        int cnt = end - base; if (cnt > 32) cnt = 32;
        int s = 0; float v = 0.f;
        if (lane < cnt) { s = __ldcs(g_srcs + base + lane); v = __ldcs(g_vals + base + lane); }
        for (int k = 0; k < cnt; k++) {
            int   sk = __shfl_sync(0xffffffffu, s, k);
            float vk = __shfl_sync(0xffffffffu, v, k);
            const float4* hp = (const float4*)(H + (size_t)sk * DIM);
            fma4(a0, vk, hp[lane]);
            fma4(a1, vk, hp[lane + 32]);
            fma4(a2, vk, hp[lane + 64]);
            fma4(a3, vk, hp[lane + 96]);
        }
    }
}

__device__ __forceinline__ void store_split(size_t off, float4 a) {
    __nv_bfloat16 hx = __float2bfloat16(a.x), hy = __float2bfloat16(a.y);
    __nv_bfloat16 hz = __float2bfloat16(a.z), hw = __float2bfloat16(a.w);
    ushort4 h = make_ushort4(__bfloat16_as_ushort(hx), __bfloat16_as_ushort(hy),
                             __bfloat16_as_ushort(hz), __bfloat16_as_ushort(hw));
    __nv_bfloat16 lx = __float2bfloat16(a.x - __bfloat162float(hx));
    __nv_bfloat16 ly = __float2bfloat16(a.y - __bfloat162float(hy));
    __nv_bfloat16 lz = __float2bfloat16(a.z - __bfloat162float(hz));
    __nv_bfloat16 lw = __float2bfloat16(a.w - __bfloat162float(hw));
    ushort4 l = make_ushort4(__bfloat16_as_ushort(lx), __bfloat16_as_ushort(ly),
                             __bfloat16_as_ushort(lz), __bfloat16_as_ushort(lw));
    *(ushort4*)(g_h1hi + off) = h;
    *(ushort4*)(g_h1lo + off) = l;
}

// ---------------- FUSED: spmm1(+relu+split) then gemm2 per 128-row block ------
// Phase 1 (memory-bound) and phase 2 (tensor-bound) of different CTAs overlap.
__global__ __launch_bounds__(256, 2) void fused_spmm_gemm_kernel(
    const float* __restrict__ H,
    const __nv_bfloat16* __restrict__ Bhi, const __nv_bfloat16* __restrict__ Blo,
    const float* __restrict__ bias, float* __restrict__ C)
{
    extern __shared__ char sm[];
    const uint32_t sbase = smem_u32(sm);
    const int tid  = threadIdx.x;
    const int warp = tid >> 5;
    const int lane = tid & 31;
    const int m0 = blockIdx.x * 128;

    // phase 1: each warp gathers 16 dst rows -> h1 hi/lo (global, CTA-private)
    for (int rr = warp * 16; rr < warp * 16 + 16; ++rr) {
        int row = m0 + rr;
        if (row >= N_NODES) break;
        float4 a0 = make_float4(0.f, 0.f, 0.f, 0.f), a1 = a0, a2 = a0, a3 = a0;
        gather_row(H, g_row_ptr[row], g_row_ptr[row + 1], lane, a0, a1, a2, a3);
        size_t base = (size_t)row * DIM;
        store_split(base + 4 * (size_t)lane,        relu4(a0));
        store_split(base + 4 * (size_t)(lane + 32), relu4(a1));
        store_split(base + 4 * (size_t)(lane + 64), relu4(a2));
        store_split(base + 4 * (size_t)(lane + 96), relu4(a3));
    }
    __syncthreads();   // CTA-scope fence: h1 rows visible; cp.async.cg reads L2

    // phase 2: gemm2 for rows [m0, m0+128), all 4 n-blocks
    for (int nb = 0; nb < 4; ++nb) {
        gemm_block_128x128(sbase, g_h1hi, g_h1lo, Bhi, Blo, bias, C,
                           m0, nb * 128, tid);
    }
}

// layer-2 SpMM: fp32 gather -> relu -> fp32 output (final, streamed)
__global__ __launch_bounds__(256) void spmm_f32_kernel(const float* __restrict__ H,
                                                       float* __restrict__ out) {
    int row  = (blockIdx.x * blockDim.x + threadIdx.x) >> 5;
    int lane = threadIdx.x & 31;
    if (row >= N_NODES) return;
    float4 a0 = make_float4(0.f, 0.f, 0.f, 0.f), a1 = a0, a2 = a0, a3 = a0;
    gather_row(H, g_row_ptr[row], g_row_ptr[row + 1], lane, a0, a1, a2, a3);
    float4* op = (float4*)(out + (size_t)row * DIM);
    __stcs(op + lane,      relu4(a0));
    __stcs(op + lane + 32, relu4(a1));
    __stcs(op + lane + 64, relu4(a2));
    __stcs(op + lane + 96, relu4(a3));
}

// ---------------- launcher ----------------------------------------------------
extern "C" void kernel_launch(void* const* d_in, const int* in_sizes, int n_in,
                              void* d_out, int out_size)
{
    const float* x    = (const float*)d_in[0];
    const int*   asrc = (const int*)  d_in[1];
    const int*   adst = (const int*)  d_in[2];
    const float* aval = (const float*)d_in[3];
    const float* W1   = (const float*)d_in[4];
    const float* b1   = (const float*)d_in[5];
    const float* W2   = (const float*)d_in[6];
    const float* b2   = (const float*)d_in[7];
    float* out = (float*)d_out;

    float *bufA, *bufC;
    __nv_bfloat16 *xhi, *xlo, *w1thi, *w1tlo, *w2thi, *w2tlo;
    cudaGetSymbolAddress((void**)&bufA,  g_bufA);
    cudaGetSymbolAddress((void**)&bufC,  g_bufC);
    cudaGetSymbolAddress((void**)&xhi,   g_xhi);
    cudaGetSymbolAddress((void**)&xlo,   g_xlo);
    cudaGetSymbolAddress((void**)&w1thi, g_w1thi);
    cudaGetSymbolAddress((void**)&w1tlo, g_w1tlo);
    cudaGetSymbolAddress((void**)&w2thi, g_w2thi);
    cudaGetSymbolAddress((void**)&w2tlo, g_w2tlo);

    cudaFuncSetAttribute(gemm_mma_kernel, cudaFuncAttributeMaxDynamicSharedMemorySize,
                         GEMM_SMEM);
    cudaFuncSetAttribute(fused_spmm_gemm_kernel, cudaFuncAttributeMaxDynamicSharedMemorySize,
                         GEMM_SMEM);

    // prep + gemm1 (gemm1 at profiled slot idx 3)
    wsplit_kernel<<<(DIM * DIM + 255) / 256, 256>>>(W1, w1thi, w1tlo);
    wsplit_kernel<<<(DIM * DIM + 255) / 256, 256>>>(W2, w2thi, w2tlo);
    {
        size_t total = (size_t)M_PAD * DIM / 4;
        split_x_kernel<<<(unsigned)((total + 255) / 256), 256>>>(x);
    }
    dim3 ggrid(DIM / 128, M_PAD / 128);   // n fastest
    gemm_mma_kernel<<<ggrid, 256, GEMM_SMEM>>>(xhi, xlo, w1thi, w1tlo, b1, bufA);

    // CSR build
    zero_counts_kernel<<<(N_NODES + 255) / 256, 256>>>();
    hist_kernel<<<(N_EDGES + 255) / 256, 256>>>(adst);
    scan_kernel<<<1, 1024>>>();
    scatter_kernel<<<(N_EDGES + 255) / 256, 256>>>(asrc, adst, aval);

    // fused spmm1 + gemm2
    fused_spmm_gemm_kernel<<<M_PAD / 128, 256, GEMM_SMEM>>>(bufA, w2thi, w2tlo, b2, bufC);

    // spmm2 -> out
    spmm_f32_kernel<<<(N_NODES + 7) / 8, 256>>>(bufC, out);
}

// round 8
// speedup vs baseline: 1.5380x; 1.5380x over previous
#include <cuda_runtime.h>
#include <cuda_bf16.h>
#include <cuda_fp16.h>
#include <cstdint>
#include <cstddef>

#define N_NODES 100000
#define M_PAD   100096            // 782 * 128
#define N_EDGES 3200000
#define DIM 512

// ---------------- scratch (device globals; no runtime allocation) ----------
__device__ __half        g_h16[(size_t)M_PAD * DIM];     // gemm1/gemm2 fp16 out (reused)
__device__ __nv_bfloat16 g_xhi[(size_t)M_PAD * DIM];
__device__ __nv_bfloat16 g_xlo[(size_t)M_PAD * DIM];
__device__ __nv_bfloat16 g_h1hi[(size_t)M_PAD * DIM];    // pad rows stay zero-init
__device__ __nv_bfloat16 g_h1lo[(size_t)M_PAD * DIM];
__device__ __nv_bfloat16 g_w1thi[DIM * DIM];
__device__ __nv_bfloat16 g_w1tlo[DIM * DIM];
__device__ __nv_bfloat16 g_w2thi[DIM * DIM];
__device__ __nv_bfloat16 g_w2tlo[DIM * DIM];
__device__ int   g_row_ptr[N_NODES + 1];
__device__ int   g_counts[N_NODES];
__device__ int   g_srcs[N_EDGES];
__device__ float g_vals[N_EDGES];

// ---------------- PTX helpers ----------------------------------------------
__device__ __forceinline__ uint32_t smem_u32(const void* p) {
    uint32_t a;
    asm("{ .reg .u64 t; cvta.to.shared.u64 t, %1; cvt.u32.u64 %0, t; }" : "=r"(a) : "l"(p));
    return a;
}

#define CP_ASYNC16(smaddr, gptr) \
    asm volatile("cp.async.cg.shared.global [%0], [%1], 16;" :: "r"(smaddr), "l"(gptr))
#define CP_COMMIT() asm volatile("cp.async.commit_group;" ::: "memory")
#define CP_WAIT(N)  asm volatile("cp.async.wait_group %0;" :: "n"(N) : "memory")

#define LDSM4(R0, R1, R2, R3, addr) \
    asm volatile("ldmatrix.sync.aligned.m8n8.x4.shared.b16 {%0,%1,%2,%3}, [%4];" \
                 : "=r"(R0), "=r"(R1), "=r"(R2), "=r"(R3) : "r"(addr))

#define MMA16816(C, A, B0, B1) \
    asm volatile("mma.sync.aligned.m16n8k16.row.col.f32.bf16.bf16.f32 " \
                 "{%0,%1,%2,%3}, {%4,%5,%6,%7}, {%8,%9}, {%0,%1,%2,%3};" \
                 : "+f"((C)[0]), "+f"((C)[1]), "+f"((C)[2]), "+f"((C)[3]) \
                 : "r"((A)[0]), "r"((A)[1]), "r"((A)[2]), "r"((A)[3]), \
                   "r"(B0), "r"(B1))

// ---------------- CSR build -------------------------------------------------
__global__ void zero_counts_kernel() {
    int i = blockIdx.x * blockDim.x + threadIdx.x;
    if (i < N_NODES) g_counts[i] = 0;
}

__global__ void hist_kernel(const int* __restrict__ dst) {
    int e = blockIdx.x * blockDim.x + threadIdx.x;
    if (e < N_EDGES) atomicAdd(&g_counts[__ldcs(dst + e)], 1);
}

__global__ __launch_bounds__(1024) void scan_kernel() {
    __shared__ int partials[1024];
    int tid = threadIdx.x;
    const int CHUNK = (N_NODES + 1023) / 1024;
    int b = tid * CHUNK;
    int e = b + CHUNK; if (e > N_NODES) e = N_NODES;
    if (b > N_NODES) b = N_NODES;
    int sum = 0;
    for (int i = b; i < e; i++) sum += g_counts[i];
    partials[tid] = sum;
    __syncthreads();
    for (int off = 1; off < 1024; off <<= 1) {
        int t = (tid >= off) ? partials[tid - off] : 0;
        __syncthreads();
        partials[tid] += t;
        __syncthreads();
    }
    int run = partials[tid] - sum;
    for (int i = b; i < e; i++) {
        g_row_ptr[i] = run;
        run += g_counts[i];
        g_counts[i] = 0;
    }
    if (tid == 1023) g_row_ptr[N_NODES] = partials[1023];
}

__global__ void scatter_kernel(const int* __restrict__ src, const int* __restrict__ dst,
                               const float* __restrict__ val) {
    int e = blockIdx.x * blockDim.x + threadIdx.x;
    if (e >= N_EDGES) return;
    int d = __ldcs(dst + e);
    int pos = g_row_ptr[d] + atomicAdd(&g_counts[d], 1);
    g_srcs[pos] = __ldcs(src + e);
    g_vals[pos] = __ldcs(val + e);
}

// ---------------- input prep: bf16 hi/lo splits ------------------------------
__global__ void split_x_kernel(const float* __restrict__ x) {
    size_t i = (size_t)blockIdx.x * blockDim.x + threadIdx.x;  // float4 index
    const size_t total = (size_t)M_PAD * DIM / 4;
    if (i >= total) return;
    size_t row = i / (DIM / 4);
    float4 v = make_float4(0.f, 0.f, 0.f, 0.f);
    if (row < N_NODES) v = ((const float4*)x)[i];
    __nv_bfloat16 hx = __float2bfloat16(v.x), hy = __float2bfloat16(v.y);
    __nv_bfloat16 hz = __float2bfloat16(v.z), hw = __float2bfloat16(v.w);
    ushort4 h = make_ushort4(__bfloat16_as_ushort(hx), __bfloat16_as_ushort(hy),
                             __bfloat16_as_ushort(hz), __bfloat16_as_ushort(hw));
    __nv_bfloat16 lx = __float2bfloat16(v.x - __bfloat162float(hx));
    __nv_bfloat16 ly = __float2bfloat16(v.y - __bfloat162float(hy));
    __nv_bfloat16 lz = __float2bfloat16(v.z - __bfloat162float(hz));
    __nv_bfloat16 lw = __float2bfloat16(v.w - __bfloat162float(hw));
    ushort4 l = make_ushort4(__bfloat16_as_ushort(lx), __bfloat16_as_ushort(ly),
                             __bfloat16_as_ushort(lz), __bfloat16_as_ushort(lw));
    ((ushort4*)g_xhi)[i] = h;
    ((ushort4*)g_xlo)[i] = l;
}

// W[k][n] -> Wt[n][k], split hi/lo
__global__ void wsplit_kernel(const float* __restrict__ W,
                              __nv_bfloat16* __restrict__ hi, __nv_bfloat16* __restrict__ lo) {
    int idx = blockIdx.x * blockDim.x + threadIdx.x;
    if (idx >= DIM * DIM) return;
    int k = idx >> 9, n = idx & 511;
    float v = W[idx];
    __nv_bfloat16 h = __float2bfloat16(v);
    __nv_bfloat16 l = __float2bfloat16(v - __bfloat162float(h));
    hi[n * DIM + k] = h;
    lo[n * DIM + k] = l;
}

// ---------------- HMMA bf16-split GEMM (R4 config), fp16 output --------------
#define BK 32
#define ROWB 80
#define OFF_AHI 0
#define OFF_ALO 10240
#define OFF_BHI 20480
#define OFF_BLO 30720
#define STAGE_BYTES 40960
#define GEMM_SMEM (2 * STAGE_BYTES)
#define NIT (DIM / BK)               // 16

__device__ __forceinline__ void stage_load(
    uint32_t sbase, int stage,
    const __nv_bfloat16* __restrict__ Ahi, const __nv_bfloat16* __restrict__ Alo,
    const __nv_bfloat16* __restrict__ Bhi, const __nv_bfloat16* __restrict__ Blo,
    int m0, int n0, int k0, int tid)
{
    uint32_t s0 = sbase + (uint32_t)stage * STAGE_BYTES;
#pragma unroll
    for (int i = tid; i < 512; i += 256) {
        int r = i >> 2, s = i & 3;
        uint32_t so = (uint32_t)r * ROWB + (uint32_t)s * 16u;
        const char* ga = (const char*)(Ahi + (size_t)(m0 + r) * DIM + k0) + s * 16;
        const char* gb = (const char*)(Alo + (size_t)(m0 + r) * DIM + k0) + s * 16;
        const char* gc = (const char*)(Bhi + (size_t)(n0 + r) * DIM + k0) + s * 16;
        const char* gd = (const char*)(Blo + (size_t)(n0 + r) * DIM + k0) + s * 16;
        CP_ASYNC16(s0 + OFF_AHI + so, ga);
        CP_ASYNC16(s0 + OFF_ALO + so, gb);
        CP_ASYNC16(s0 + OFF_BHI + so, gc);
        CP_ASYNC16(s0 + OFF_BLO + so, gd);
    }
}

__global__ __launch_bounds__(256, 2) void gemm_mma_kernel(
    const __nv_bfloat16* __restrict__ Ahi, const __nv_bfloat16* __restrict__ Alo,
    const __nv_bfloat16* __restrict__ Bhi, const __nv_bfloat16* __restrict__ Blo,
    const float* __restrict__ bias, __half* __restrict__ C)
{
    extern __shared__ char sm[];
    const uint32_t sbase = smem_u32(sm);
    const int tid  = threadIdx.x;
    const int warp = tid >> 5;
    const int lane = tid & 31;
    const int wm = warp & 1;
    const int wn = warp >> 1;
    const int n0 = blockIdx.x * 128;      // n fastest -> wave shares A rows
    const int m0 = blockIdx.y * 128;

    float acc[4][4][4];
#pragma unroll
    for (int a = 0; a < 4; a++)
#pragma unroll
        for (int b = 0; b < 4; b++)
#pragma unroll
            for (int c = 0; c < 4; c++) acc[a][b][c] = 0.f;

    const int a_row = lane & 15;
    const int a_koff = (lane >> 4) * 8;
    const int b_g = lane >> 3;
    const int b_nloc = ((b_g >> 1) << 3) + (lane & 7);
    const int b_koff = (b_g & 1) * 8;

    stage_load(sbase, 0, Ahi, Alo, Bhi, Blo, m0, n0, 0, tid);
    CP_COMMIT();

    for (int it = 0; it < NIT; ++it) {
        if (it + 1 < NIT) {
            stage_load(sbase, (it + 1) & 1, Ahi, Alo, Bhi, Blo, m0, n0, (it + 1) * BK, tid);
            CP_COMMIT();
            CP_WAIT(1);
        } else {
            CP_WAIT(0);
        }
        __syncthreads();

        const uint32_t st = sbase + (uint32_t)(it & 1) * STAGE_BYTES;
#pragma unroll
        for (int kk = 0; kk < 2; ++kk) {
            const int k16 = kk * 16;
            uint32_t ahi[4][4], alo[4][4];
#pragma unroll
            for (int mi = 0; mi < 4; ++mi) {
                uint32_t ra = (uint32_t)(wm * 64 + mi * 16 + a_row) * ROWB
                            + (uint32_t)(k16 + a_koff) * 2;
                LDSM4(ahi[mi][0], ahi[mi][1], ahi[mi][2], ahi[mi][3], st + OFF_AHI + ra);
                LDSM4(alo[mi][0], alo[mi][1], alo[mi][2], alo[mi][3], st + OFF_ALO + ra);
            }
            uint32_t bhi[2][4], blo[2][4];
#pragma unroll
            for (int nb = 0; nb < 2; ++nb) {
                uint32_t rb = (uint32_t)(wn * 32 + nb * 16 + b_nloc) * ROWB
                            + (uint32_t)(k16 + b_koff) * 2;
                LDSM4(bhi[nb][0], bhi[nb][1], bhi[nb][2], bhi[nb][3], st + OFF_BHI + rb);
                LDSM4(blo[nb][0], blo[nb][1], blo[nb][2], blo[nb][3], st + OFF_BLO + rb);
            }
#pragma unroll
            for (int mi = 0; mi < 4; ++mi) {
#pragma unroll
                for (int j = 0; j < 4; ++j) {
                    const int nb = j >> 1, blk = j & 1;
                    MMA16816(acc[mi][j], ahi[mi], bhi[nb][blk * 2], bhi[nb][blk * 2 + 1]);
                    MMA16816(acc[mi][j], ahi[mi], blo[nb][blk * 2], blo[nb][blk * 2 + 1]);
                    MMA16816(acc[mi][j], alo[mi], bhi[nb][blk * 2], bhi[nb][blk * 2 + 1]);
                }
            }
        }
        __syncthreads();
    }

    // epilogue: bias add + fp16 store (plain stores -> lands in L2 for SpMM)
#pragma unroll
    for (int mi = 0; mi < 4; ++mi) {
        int row = m0 + wm * 64 + mi * 16 + (lane >> 2);
#pragma unroll
        for (int j = 0; j < 4; ++j) {
            int col = n0 + wn * 32 + j * 8 + (lane & 3) * 2;
            float b0 = bias[col], b1 = bias[col + 1];
            __half2 v0 = __floats2half2_rn(acc[mi][j][0] + b0, acc[mi][j][1] + b1);
            __half2 v1 = __floats2half2_rn(acc[mi][j][2] + b0, acc[mi][j][3] + b1);
            *(__half2*)(C + (size_t)row * DIM + col) = v0;
            *(__half2*)(C + (size_t)(row + 8) * DIM + col) = v1;
        }
    }
}

// ---------------- SpMM (CSR by dst), fp16 gather, one warp per row -----------
// Lane owns dims [lane*8, lane*8+8) and [(lane+32)*8, (lane+32)*8+8).
struct Acc16 { float2 f[8]; };

__device__ __forceinline__ void gather_row_h(const __half* __restrict__ H,
                                             int beg, int end, int lane, Acc16& A) {
#pragma unroll
    for (int j = 0; j < 8; j++) A.f[j] = make_float2(0.f, 0.f);
    for (int base = beg; base < end; base += 32) {
        int cnt = end - base; if (cnt > 32) cnt = 32;
        int s = 0; float v = 0.f;
        if (lane < cnt) { s = __ldcs(g_srcs + base + lane); v = __ldcs(g_vals + base + lane); }
        for (int k = 0; k < cnt; k++) {
            int   sk = __shfl_sync(0xffffffffu, s, k);
            float vk = __shfl_sync(0xffffffffu, v, k);
            const uint4* hp = (const uint4*)(H + (size_t)sk * DIM);
            uint4 q0 = hp[lane];
            uint4 q1 = hp[lane + 32];
            const __half2* h0 = (const __half2*)&q0;
            const __half2* h1 = (const __half2*)&q1;
#pragma unroll
            for (int j = 0; j < 4; j++) {
                float2 f0 = __half22float2(h0[j]);
                float2 f1 = __half22float2(h1[j]);
                A.f[j].x     = fmaf(vk, f0.x, A.f[j].x);
                A.f[j].y     = fmaf(vk, f0.y, A.f[j].y);
                A.f[j + 4].x = fmaf(vk, f1.x, A.f[j + 4].x);
                A.f[j + 4].y = fmaf(vk, f1.y, A.f[j + 4].y);
            }
        }
    }
#pragma unroll
    for (int j = 0; j < 8; j++) {
        A.f[j].x = fmaxf(A.f[j].x, 0.f);
        A.f[j].y = fmaxf(A.f[j].y, 0.f);
    }
}

// layer-1: gather fp16 -> relu -> bf16 hi/lo split (gemm2 inputs)
__global__ __launch_bounds__(256) void spmm_split_kernel(const __half* __restrict__ H) {
    int row  = (blockIdx.x * blockDim.x + threadIdx.x) >> 5;
    int lane = threadIdx.x & 31;
    if (row >= N_NODES) return;
    Acc16 A;
    gather_row_h(H, g_row_ptr[row], g_row_ptr[row + 1], lane, A);
    size_t base = (size_t)row * DIM;
#pragma unroll
    for (int half = 0; half < 2; half++) {
        size_t off = base + (size_t)(lane + half * 32) * 8;
        const float* x = (const float*)&A.f[half * 4];
        ushort4 h[2], l[2];
#pragma unroll
        for (int g = 0; g < 2; g++) {
            unsigned short hh[4], ll[4];
#pragma unroll
            for (int t = 0; t < 4; t++) {
                float v = x[g * 4 + t];
                __nv_bfloat16 hb = __float2bfloat16(v);
                __nv_bfloat16 lb = __float2bfloat16(v - __bfloat162float(hb));
                hh[t] = __bfloat16_as_ushort(hb);
                ll[t] = __bfloat16_as_ushort(lb);
            }
            h[g] = make_ushort4(hh[0], hh[1], hh[2], hh[3]);
            l[g] = make_ushort4(ll[0], ll[1], ll[2], ll[3]);
        }
        __stcs((uint2*)(g_h1hi + off),     *(uint2*)&h[0]);
        __stcs((uint2*)(g_h1hi + off + 4), *(uint2*)&h[1]);
        __stcs((uint2*)(g_h1lo + off),     *(uint2*)&l[0]);
        __stcs((uint2*)(g_h1lo + off + 4), *(uint2*)&l[1]);
    }
}

// layer-2: gather fp16 -> relu -> fp32 final output
__global__ __launch_bounds__(256) void spmm_out_kernel(const __half* __restrict__ H,
                                                       float* __restrict__ out) {
    int row  = (blockIdx.x * blockDim.x + threadIdx.x) >> 5;
    int lane = threadIdx.x & 31;
    if (row >= N_NODES) return;
    Acc16 A;
    gather_row_h(H, g_row_ptr[row], g_row_ptr[row + 1], lane, A);
    float* op = out + (size_t)row * DIM;
#pragma unroll
    for (int half = 0; half < 2; half++) {
        float* p = op + (lane + half * 32) * 8;
        float4 v0 = make_float4(A.f[half * 4 + 0].x, A.f[half * 4 + 0].y,
                                A.f[half * 4 + 1].x, A.f[half * 4 + 1].y);
        float4 v1 = make_float4(A.f[half * 4 + 2].x, A.f[half * 4 + 2].y,
                                A.f[half * 4 + 3].x, A.f[half * 4 + 3].y);
        __stcs((float4*)p, v0);
        __stcs((float4*)(p + 4), v1);
    }
}

// ---------------- launcher ----------------------------------------------------
extern "C" void kernel_launch(void* const* d_in, const int* in_sizes, int n_in,
                              void* d_out, int out_size)
{
    const float* x    = (const float*)d_in[0];
    const int*   asrc = (const int*)  d_in[1];
    const int*   adst = (const int*)  d_in[2];
    const float* aval = (const float*)d_in[3];
    const float* W1   = (const float*)d_in[4];
    const float* b1   = (const float*)d_in[5];
    const float* W2   = (const float*)d_in[6];
    const float* b2   = (const float*)d_in[7];
    float* out = (float*)d_out;

    __half* h16;
    __nv_bfloat16 *xhi, *xlo, *h1hi, *h1lo, *w1thi, *w1tlo, *w2thi, *w2tlo;
    cudaGetSymbolAddress((void**)&h16,   g_h16);
    cudaGetSymbolAddress((void**)&xhi,   g_xhi);
    cudaGetSymbolAddress((void**)&xlo,   g_xlo);
    cudaGetSymbolAddress((void**)&h1hi,  g_h1hi);
    cudaGetSymbolAddress((void**)&h1lo,  g_h1lo);
    cudaGetSymbolAddress((void**)&w1thi, g_w1thi);
    cudaGetSymbolAddress((void**)&w1tlo, g_w1tlo);
    cudaGetSymbolAddress((void**)&w2thi, g_w2thi);
    cudaGetSymbolAddress((void**)&w2tlo, g_w2tlo);

    cudaFuncSetAttribute(gemm_mma_kernel, cudaFuncAttributeMaxDynamicSharedMemorySize,
                         GEMM_SMEM);

    dim3 ggrid(DIM / 128, M_PAD / 128);   // n fastest

    // prep + gemm1 (gemm1 at profiled slot idx 3)
    wsplit_kernel<<<(DIM * DIM + 255) / 256, 256>>>(W1, w1thi, w1tlo);
    wsplit_kernel<<<(DIM * DIM + 255) / 256, 256>>>(W2, w2thi, w2tlo);
    {
        size_t total = (size_t)M_PAD * DIM / 4;
        split_x_kernel<<<(unsigned)((total + 255) / 256), 256>>>(x);
    }
    gemm_mma_kernel<<<ggrid, 256, GEMM_SMEM>>>(xhi, xlo, w1thi, w1tlo, b1, h16);

    // CSR build
    zero_counts_kernel<<<(N_NODES + 255) / 256, 256>>>();
    hist_kernel<<<(N_EDGES + 255) / 256, 256>>>(adst);
    scan_kernel<<<1, 1024>>>();
    scatter_kernel<<<(N_EDGES + 255) / 256, 256>>>(asrc, adst, aval);

    // Layer 1 aggregate: fp16 gather -> bf16 hi/lo split
    spmm_split_kernel<<<(N_NODES + 7) / 8, 256>>>(h16);

    // Layer 2
    gemm_mma_kernel<<<ggrid, 256, GEMM_SMEM>>>(h1hi, h1lo, w2thi, w2tlo, b2, h16);
    spmm_out_kernel<<<(N_NODES + 7) / 8, 256>>>(h16, out);
}

// round 9
// speedup vs baseline: 1.8189x; 1.1826x over previous
#include <cuda_runtime.h>
#include <cuda_fp16.h>
#include <cstdint>
#include <cstddef>

#define N_NODES 100000
#define M_PAD   100096            // 782 * 128
#define N_EDGES 3200000
#define DIM 512

// ---------------- scratch (device globals; no runtime allocation) ----------
__device__ __half g_x16[(size_t)M_PAD * DIM];    // fp16(x)
__device__ __half g_o16[(size_t)M_PAD * DIM];    // gemm outputs (both layers)
__device__ __half g_h16[(size_t)M_PAD * DIM];    // spmm1 output (gemm2 input)
__device__ __half g_w1thi[DIM * DIM];
__device__ __half g_w1tlo[DIM * DIM];
__device__ __half g_w2thi[DIM * DIM];
__device__ __half g_w2tlo[DIM * DIM];
__device__ int   g_row_ptr[N_NODES + 1];
__device__ int   g_counts[N_NODES];
__device__ int   g_srcs[N_EDGES];
__device__ float g_vals[N_EDGES];

// ---------------- PTX helpers ----------------------------------------------
__device__ __forceinline__ uint32_t smem_u32(const void* p) {
    uint32_t a;
    asm("{ .reg .u64 t; cvta.to.shared.u64 t, %1; cvt.u32.u64 %0, t; }" : "=r"(a) : "l"(p));
    return a;
}

#define CP_ASYNC16(smaddr, gptr) \
    asm volatile("cp.async.cg.shared.global [%0], [%1], 16;" :: "r"(smaddr), "l"(gptr))
#define CP_COMMIT() asm volatile("cp.async.commit_group;" ::: "memory")
#define CP_WAIT(N)  asm volatile("cp.async.wait_group %0;" :: "n"(N) : "memory")

#define LDSM4(R0, R1, R2, R3, addr) \
    asm volatile("ldmatrix.sync.aligned.m8n8.x4.shared.b16 {%0,%1,%2,%3}, [%4];" \
                 : "=r"(R0), "=r"(R1), "=r"(R2), "=r"(R3) : "r"(addr))

#define MMA16816F(C, A, B0, B1) \
    asm volatile("mma.sync.aligned.m16n8k16.row.col.f32.f16.f16.f32 " \
                 "{%0,%1,%2,%3}, {%4,%5,%6,%7}, {%8,%9}, {%0,%1,%2,%3};" \
                 : "+f"((C)[0]), "+f"((C)[1]), "+f"((C)[2]), "+f"((C)[3]) \
                 : "r"((A)[0]), "r"((A)[1]), "r"((A)[2]), "r"((A)[3]), \
                   "r"(B0), "r"(B1))

// ---------------- CSR build -------------------------------------------------
__global__ void zero_counts_kernel() {
    int i = blockIdx.x * blockDim.x + threadIdx.x;
    if (i < N_NODES) g_counts[i] = 0;
}

__global__ void hist_kernel(const int* __restrict__ dst) {
    int e = blockIdx.x * blockDim.x + threadIdx.x;
    if (e < N_EDGES) atomicAdd(&g_counts[__ldcs(dst + e)], 1);
}

__global__ __launch_bounds__(1024) void scan_kernel() {
    __shared__ int partials[1024];
    int tid = threadIdx.x;
    const int CHUNK = (N_NODES + 1023) / 1024;
    int b = tid * CHUNK;
    int e = b + CHUNK; if (e > N_NODES) e = N_NODES;
    if (b > N_NODES) b = N_NODES;
    int sum = 0;
    for (int i = b; i < e; i++) sum += g_counts[i];
    partials[tid] = sum;
    __syncthreads();
    for (int off = 1; off < 1024; off <<= 1) {
        int t = (tid >= off) ? partials[tid - off] : 0;
        __syncthreads();
        partials[tid] += t;
        __syncthreads();
    }
    int run = partials[tid] - sum;
    for (int i = b; i < e; i++) {
        g_row_ptr[i] = run;
        run += g_counts[i];
        g_counts[i] = 0;
    }
    if (tid == 1023) g_row_ptr[N_NODES] = partials[1023];
}

__global__ void scatter_kernel(const int* __restrict__ src, const int* __restrict__ dst,
                               const float* __restrict__ val) {
    int e = blockIdx.x * blockDim.x + threadIdx.x;
    if (e >= N_EDGES) return;
    int d = __ldcs(dst + e);
    int pos = g_row_ptr[d] + atomicAdd(&g_counts[d], 1);
    g_srcs[pos] = __ldcs(src + e);
    g_vals[pos] = __ldcs(val + e);
}

// ---------------- input prep -------------------------------------------------
__global__ void convert_x_kernel(const float* __restrict__ x) {
    size_t i = (size_t)blockIdx.x * blockDim.x + threadIdx.x;  // float4 index
    const size_t total = (size_t)M_PAD * DIM / 4;
    if (i >= total) return;
    size_t row = i / (DIM / 4);
    float4 v = make_float4(0.f, 0.f, 0.f, 0.f);
    if (row < N_NODES) v = ((const float4*)x)[i];
    __half2 h0 = __floats2half2_rn(v.x, v.y);
    __half2 h1 = __floats2half2_rn(v.z, v.w);
    uint2 pk;
    pk.x = *(uint32_t*)&h0;
    pk.y = *(uint32_t*)&h1;
    ((uint2*)g_x16)[i] = pk;
}

// W[k][n] -> Wt[n][k], fp16 hi/lo split
__global__ void wsplit_kernel(const float* __restrict__ W,
                              __half* __restrict__ hi, __half* __restrict__ lo) {
    int idx = blockIdx.x * blockDim.x + threadIdx.x;
    if (idx >= DIM * DIM) return;
    int k = idx >> 9, n = idx & 511;
    float v = W[idx];
    __half h = __float2half_rn(v);
    __half l = __float2half_rn(v - __half2float(h));
    hi[n * DIM + k] = h;
    lo[n * DIM + k] = l;
}

// ---------------- HMMA fp16 2-product GEMM -----------------------------------
// C[.,512](fp16) = A(fp16) @ (Whi+Wlo)^T(stored [n][k]) + bias, fp32 accum.
// CTA 128x128, 8 warps (warp 64x32), K-chunk 32, double-buffered smem.
#define BK 32
#define ROWB 80
#define OFF_A   0
#define OFF_BHI 10240
#define OFF_BLO 20480
#define STAGE_BYTES 30720
#define GEMM_SMEM (2 * STAGE_BYTES)
#define NIT (DIM / BK)               // 16

__device__ __forceinline__ void stage_load(
    uint32_t sbase, int stage,
    const __half* __restrict__ A,
    const __half* __restrict__ Bhi, const __half* __restrict__ Blo,
    int m0, int n0, int k0, int tid)
{
    uint32_t s0 = sbase + (uint32_t)stage * STAGE_BYTES;
#pragma unroll
    for (int i = tid; i < 512; i += 256) {
        int r = i >> 2, s = i & 3;
        uint32_t so = (uint32_t)r * ROWB + (uint32_t)s * 16u;
        const char* ga = (const char*)(A   + (size_t)(m0 + r) * DIM + k0) + s * 16;
        const char* gc = (const char*)(Bhi + (size_t)(n0 + r) * DIM + k0) + s * 16;
        const char* gd = (const char*)(Blo + (size_t)(n0 + r) * DIM + k0) + s * 16;
        CP_ASYNC16(s0 + OFF_A   + so, ga);
        CP_ASYNC16(s0 + OFF_BHI + so, gc);
        CP_ASYNC16(s0 + OFF_BLO + so, gd);
    }
}

__global__ __launch_bounds__(256, 2) void gemm_f16_kernel(
    const __half* __restrict__ A,
    const __half* __restrict__ Bhi, const __half* __restrict__ Blo,
    const float* __restrict__ bias, __half* __restrict__ C)
{
    extern __shared__ char sm[];
    const uint32_t sbase = smem_u32(sm);
    const int tid  = threadIdx.x;
    const int warp = tid >> 5;
    const int lane = tid & 31;
    const int wm = warp & 1;
    const int wn = warp >> 1;
    const int n0 = blockIdx.x * 128;      // n fastest -> wave shares A rows
    const int m0 = blockIdx.y * 128;

    float acc[4][4][4];
#pragma unroll
    for (int a = 0; a < 4; a++)
#pragma unroll
        for (int b = 0; b < 4; b++)
#pragma unroll
            for (int c = 0; c < 4; c++) acc[a][b][c] = 0.f;

    const int a_row = lane & 15;
    const int a_koff = (lane >> 4) * 8;
    const int b_g = lane >> 3;
    const int b_nloc = ((b_g >> 1) << 3) + (lane & 7);
    const int b_koff = (b_g & 1) * 8;

    stage_load(sbase, 0, A, Bhi, Blo, m0, n0, 0, tid);
    CP_COMMIT();

    for (int it = 0; it < NIT; ++it) {
        if (it + 1 < NIT) {
            stage_load(sbase, (it + 1) & 1, A, Bhi, Blo, m0, n0, (it + 1) * BK, tid);
            CP_COMMIT();
            CP_WAIT(1);
        } else {
            CP_WAIT(0);
        }
        __syncthreads();

        const uint32_t st = sbase + (uint32_t)(it & 1) * STAGE_BYTES;
#pragma unroll
        for (int kk = 0; kk < 2; ++kk) {
            const int k16 = kk * 16;
            uint32_t av[4][4];
#pragma unroll
            for (int mi = 0; mi < 4; ++mi) {
                uint32_t ra = (uint32_t)(wm * 64 + mi * 16 + a_row) * ROWB
                            + (uint32_t)(k16 + a_koff) * 2;
                LDSM4(av[mi][0], av[mi][1], av[mi][2], av[mi][3], st + OFF_A + ra);
            }
            uint32_t bhi[2][4], blo[2][4];
#pragma unroll
            for (int nb = 0; nb < 2; ++nb) {
                uint32_t rb = (uint32_t)(wn * 32 + nb * 16 + b_nloc) * ROWB
                            + (uint32_t)(k16 + b_koff) * 2;
                LDSM4(bhi[nb][0], bhi[nb][1], bhi[nb][2], bhi[nb][3], st + OFF_BHI + rb);
                LDSM4(blo[nb][0], blo[nb][1], blo[nb][2], blo[nb][3], st + OFF_BLO + rb);
            }
#pragma unroll
            for (int mi = 0; mi < 4; ++mi) {
#pragma unroll
                for (int j = 0; j < 4; ++j) {
                    const int nb = j >> 1, blk = j & 1;
                    MMA16816F(acc[mi][j], av[mi], bhi[nb][blk * 2], bhi[nb][blk * 2 + 1]);
                    MMA16816F(acc[mi][j], av[mi], blo[nb][blk * 2], blo[nb][blk * 2 + 1]);
                }
            }
        }
        __syncthreads();
    }

    // epilogue: bias add + fp16 store (plain stores -> lands in L2 for SpMM)
#pragma unroll
    for (int mi = 0; mi < 4; ++mi) {
        int row = m0 + wm * 64 + mi * 16 + (lane >> 2);
#pragma unroll
        for (int j = 0; j < 4; ++j) {
            int col = n0 + wn * 32 + j * 8 + (lane & 3) * 2;
            float b0 = bias[col], b1 = bias[col + 1];
            __half2 v0 = __floats2half2_rn(acc[mi][j][0] + b0, acc[mi][j][1] + b1);
            __half2 v1 = __floats2half2_rn(acc[mi][j][2] + b0, acc[mi][j][3] + b1);
            *(__half2*)(C + (size_t)row * DIM + col) = v0;
            *(__half2*)(C + (size_t)(row + 8) * DIM + col) = v1;
        }
    }
}

// ---------------- SpMM (CSR by dst), fp16 gather, one warp per row -----------
// Lane owns dims [lane*8, +8) and [(lane+32)*8, +8).
struct Acc16 { float2 f[8]; };

__device__ __forceinline__ void gather_row_h(const __half* __restrict__ H,
                                             int beg, int end, int lane, Acc16& A) {
#pragma unroll
    for (int j = 0; j < 8; j++) A.f[j] = make_float2(0.f, 0.f);
    for (int base = beg; base < end; base += 32) {
        int cnt = end - base; if (cnt > 32) cnt = 32;
        int s = 0; float v = 0.f;
        if (lane < cnt) { s = __ldcs(g_srcs + base + lane); v = __ldcs(g_vals + base + lane); }
        for (int k = 0; k < cnt; k++) {
            int   sk = __shfl_sync(0xffffffffu, s, k);
            float vk = __shfl_sync(0xffffffffu, v, k);
            const uint4* hp = (const uint4*)(H + (size_t)sk * DIM);
            uint4 q0 = hp[lane];
            uint4 q1 = hp[lane + 32];
            const __half2* h0 = (const __half2*)&q0;
            const __half2* h1 = (const __half2*)&q1;
#pragma unroll
            for (int j = 0; j < 4; j++) {
                float2 f0 = __half22float2(h0[j]);
                float2 f1 = __half22float2(h1[j]);
                A.f[j].x     = fmaf(vk, f0.x, A.f[j].x);
                A.f[j].y     = fmaf(vk, f0.y, A.f[j].y);
                A.f[j + 4].x = fmaf(vk, f1.x, A.f[j + 4].x);
                A.f[j + 4].y = fmaf(vk, f1.y, A.f[j + 4].y);
            }
        }
    }
#pragma unroll
    for (int j = 0; j < 8; j++) {
        A.f[j].x = fmaxf(A.f[j].x, 0.f);
        A.f[j].y = fmaxf(A.f[j].y, 0.f);
    }
}

// layer-1: gather fp16 -> relu -> fp16 (gemm2 input)
__global__ __launch_bounds__(256) void spmm_h16_kernel(const __half* __restrict__ H,
                                                       __half* __restrict__ outh) {
    int row  = (blockIdx.x * blockDim.x + threadIdx.x) >> 5;
    int lane = threadIdx.x & 31;
    if (row >= N_NODES) return;
    Acc16 A;
    gather_row_h(H, g_row_ptr[row], g_row_ptr[row + 1], lane, A);
    __half* op = outh + (size_t)row * DIM;
#pragma unroll
    for (int half = 0; half < 2; half++) {
        uint4 pk;
        __half2 p0 = __floats2half2_rn(A.f[half * 4 + 0].x, A.f[half * 4 + 0].y);
        __half2 p1 = __floats2half2_rn(A.f[half * 4 + 1].x, A.f[half * 4 + 1].y);
        __half2 p2 = __floats2half2_rn(A.f[half * 4 + 2].x, A.f[half * 4 + 2].y);
        __half2 p3 = __floats2half2_rn(A.f[half * 4 + 3].x, A.f[half * 4 + 3].y);
        pk.x = *(uint32_t*)&p0; pk.y = *(uint32_t*)&p1;
        pk.z = *(uint32_t*)&p2; pk.w = *(uint32_t*)&p3;
        __stcs((uint4*)(op + (lane + half * 32) * 8), pk);
    }
}

// layer-2: gather fp16 -> relu -> fp32 final output
__global__ __launch_bounds__(256) void spmm_out_kernel(const __half* __restrict__ H,
                                                       float* __restrict__ out) {
    int row  = (blockIdx.x * blockDim.x + threadIdx.x) >> 5;
    int lane = threadIdx.x & 31;
    if (row >= N_NODES) return;
    Acc16 A;
    gather_row_h(H, g_row_ptr[row], g_row_ptr[row + 1], lane, A);
    float* op = out + (size_t)row * DIM;
#pragma unroll
    for (int half = 0; half < 2; half++) {
        float* p = op + (lane + half * 32) * 8;
        float4 v0 = make_float4(A.f[half * 4 + 0].x, A.f[half * 4 + 0].y,
                                A.f[half * 4 + 1].x, A.f[half * 4 + 1].y);
        float4 v1 = make_float4(A.f[half * 4 + 2].x, A.f[half * 4 + 2].y,
                                A.f[half * 4 + 3].x, A.f[half * 4 + 3].y);
        __stcs((float4*)p, v0);
        __stcs((float4*)(p + 4), v1);
    }
}

// ---------------- launcher ----------------------------------------------------
extern "C" void kernel_launch(void* const* d_in, const int* in_sizes, int n_in,
                              void* d_out, int out_size)
{
    const float* x    = (const float*)d_in[0];
    const int*   asrc = (const int*)  d_in[1];
    const int*   adst = (const int*)  d_in[2];
    const float* aval = (const float*)d_in[3];
    const float* W1   = (const float*)d_in[4];
    const float* b1   = (const float*)d_in[5];
    const float* W2   = (const float*)d_in[6];
    const float* b2   = (const float*)d_in[7];
    float* out = (float*)d_out;

    __half *x16, *o16, *h16, *w1thi, *w1tlo, *w2thi, *w2tlo;
    cudaGetSymbolAddress((void**)&x16,   g_x16);
    cudaGetSymbolAddress((void**)&o16,   g_o16);
    cudaGetSymbolAddress((void**)&h16,   g_h16);
    cudaGetSymbolAddress((void**)&w1thi, g_w1thi);
    cudaGetSymbolAddress((void**)&w1tlo, g_w1tlo);
    cudaGetSymbolAddress((void**)&w2thi, g_w2thi);
    cudaGetSymbolAddress((void**)&w2tlo, g_w2tlo);

    cudaFuncSetAttribute(gemm_f16_kernel, cudaFuncAttributeMaxDynamicSharedMemorySize,
                         GEMM_SMEM);

    dim3 ggrid(DIM / 128, M_PAD / 128);   // n fastest

    // prep + gemm1 (gemm1 at profiled slot idx 3)
    wsplit_kernel<<<(DIM * DIM + 255) / 256, 256>>>(W1, w1thi, w1tlo);
    wsplit_kernel<<<(DIM * DIM + 255) / 256, 256>>>(W2, w2thi, w2tlo);
    {
        size_t total = (size_t)M_PAD * DIM / 4;
        convert_x_kernel<<<(unsigned)((total + 255) / 256), 256>>>(x);
    }
    gemm_f16_kernel<<<ggrid, 256, GEMM_SMEM>>>(x16, w1thi, w1tlo, b1, o16);

    // CSR build
    zero_counts_kernel<<<(N_NODES + 255) / 256, 256>>>();
    hist_kernel<<<(N_EDGES + 255) / 256, 256>>>(adst);
    scan_kernel<<<1, 1024>>>();
    scatter_kernel<<<(N_EDGES + 255) / 256, 256>>>(asrc, adst, aval);

    // Layer 1 aggregate: fp16 gather -> fp16 h1
    spmm_h16_kernel<<<(N_NODES + 7) / 8, 256>>>(o16, h16);

    // Layer 2
    gemm_f16_kernel<<<ggrid, 256, GEMM_SMEM>>>(h16, w2thi, w2tlo, b2, o16);
    spmm_out_kernel<<<(N_NODES + 7) / 8, 256>>>(o16, out);
}

// round 10
// speedup vs baseline: 2.1330x; 1.1727x over previous
#include <cuda_runtime.h>
#include <cuda_fp16.h>
#include <cstdint>
#include <cstddef>

#define N_NODES 100000
#define M_PAD   100096            // 782 * 128
#define N_EDGES 3200000
#define DIM 512

// ---------------- scratch (device globals; no runtime allocation) ----------
__device__ __half g_x16[(size_t)M_PAD * DIM];    // fp16(x)
__device__ __half g_o16[(size_t)M_PAD * DIM];    // gemm outputs (both layers)
__device__ __half g_h16[(size_t)M_PAD * DIM];    // spmm1 output (gemm2 input)
__device__ __half g_w1t[DIM * DIM];
__device__ __half g_w2t[DIM * DIM];
__device__ int   g_row_ptr[N_NODES + 1];
__device__ int   g_counts[N_NODES];
__device__ int   g_srcs[N_EDGES];
__device__ float g_vals[N_EDGES];

// ---------------- PTX helpers ----------------------------------------------
__device__ __forceinline__ uint32_t smem_u32(const void* p) {
    uint32_t a;
    asm("{ .reg .u64 t; cvta.to.shared.u64 t, %1; cvt.u32.u64 %0, t; }" : "=r"(a) : "l"(p));
    return a;
}

#define CP_ASYNC16(smaddr, gptr) \
    asm volatile("cp.async.cg.shared.global [%0], [%1], 16;" :: "r"(smaddr), "l"(gptr))
#define CP_COMMIT() asm volatile("cp.async.commit_group;" ::: "memory")
#define CP_WAIT(N)  asm volatile("cp.async.wait_group %0;" :: "n"(N) : "memory")

#define LDSM4(R0, R1, R2, R3, addr) \
    asm volatile("ldmatrix.sync.aligned.m8n8.x4.shared.b16 {%0,%1,%2,%3}, [%4];" \
                 : "=r"(R0), "=r"(R1), "=r"(R2), "=r"(R3) : "r"(addr))

#define MMA16816F(C, A, B0, B1) \
    asm volatile("mma.sync.aligned.m16n8k16.row.col.f32.f16.f16.f32 " \
                 "{%0,%1,%2,%3}, {%4,%5,%6,%7}, {%8,%9}, {%0,%1,%2,%3};" \
                 : "+f"((C)[0]), "+f"((C)[1]), "+f"((C)[2]), "+f"((C)[3]) \
                 : "r"((A)[0]), "r"((A)[1]), "r"((A)[2]), "r"((A)[3]), \
                   "r"(B0), "r"(B1))

// ---------------- CSR pieces ------------------------------------------------
__global__ void zero_counts_kernel() {
    int i = blockIdx.x * blockDim.x + threadIdx.x;
    if (i < N_NODES) g_counts[i] = 0;
}

__global__ __launch_bounds__(1024) void scan_kernel() {
    __shared__ int partials[1024];
    int tid = threadIdx.x;
    const int CHUNK = (N_NODES + 1023) / 1024;
    int b = tid * CHUNK;
    int e = b + CHUNK; if (e > N_NODES) e = N_NODES;
    if (b > N_NODES) b = N_NODES;
    int sum = 0;
    for (int i = b; i < e; i++) sum += g_counts[i];
    partials[tid] = sum;
    __syncthreads();
    for (int off = 1; off < 1024; off <<= 1) {
        int t = (tid >= off) ? partials[tid - off] : 0;
        __syncthreads();
        partials[tid] += t;
        __syncthreads();
    }
    int run = partials[tid] - sum;
    for (int i = b; i < e; i++) {
        g_row_ptr[i] = run;
        run += g_counts[i];
        g_counts[i] = 0;
    }
    if (tid == 1023) g_row_ptr[N_NODES] = partials[1023];
}

// ---------------- merged prep: convert_x || hist || W transposes -------------
#define NB_CONV 12512     // 12512 blocks * 1024 float4 = M_PAD*DIM/4
#define NB_HIST 1568
#define NB_W    1024      // 1024 blocks * 256 = DIM*DIM
#define NB_PREP (NB_CONV + NB_HIST + 2 * NB_W)

__global__ __launch_bounds__(256) void prep_kernel(
    const float* __restrict__ x, const int* __restrict__ dst,
    const float* __restrict__ W1, const float* __restrict__ W2)
{
    int b = blockIdx.x;
    if (b < NB_CONV) {
        // x -> fp16, pad rows zero; 1024 contiguous float4 per block
#pragma unroll
        for (int j = 0; j < 4; j++) {
            size_t i = (size_t)b * 1024 + j * 256 + threadIdx.x;
            size_t row = i / (DIM / 4);
            float4 v = make_float4(0.f, 0.f, 0.f, 0.f);
            if (row < N_NODES) v = ((const float4*)x)[i];
            __half2 h0 = __floats2half2_rn(v.x, v.y);
            __half2 h1 = __floats2half2_rn(v.z, v.w);
            uint2 pk;
            pk.x = *(uint32_t*)&h0;
            pk.y = *(uint32_t*)&h1;
            ((uint2*)g_x16)[i] = pk;
        }
    } else if (b < NB_CONV + NB_HIST) {
        int gtid = (b - NB_CONV) * 256 + threadIdx.x;
        const int stride = NB_HIST * 256;
        for (int e = gtid; e < N_EDGES; e += stride)
            atomicAdd(&g_counts[__ldcs(dst + e)], 1);
    } else {
        int b3 = b - NB_CONV - NB_HIST;
        const float* W = (b3 < NB_W) ? W1 : W2;
        __half* Wt = (b3 < NB_W) ? g_w1t : g_w2t;
        int idx = (b3 & (NB_W - 1)) * 256 + threadIdx.x;
        int k = idx >> 9, n = idx & 511;
        Wt[n * DIM + k] = __float2half_rn(W[idx]);
    }
}

// ---------------- HMMA fp16 GEMM (single product) + fused CSR scatter --------
// C[.,512](fp16) = A(fp16) @ Wt^T + bias, fp32 accum.
// CTA 128x128, 8 warps (warp 64x32), K-chunk 32, double-buffered smem.
// Leading extraY block-rows perform the CSR scatter (gemm1 only).
#define BK 32
#define ROWB 80
#define OFF_A   0
#define OFF_B   10240
#define STAGE_BYTES 20480
#define GEMM_SMEM (2 * STAGE_BYTES)
#define NIT (DIM / BK)               // 16
#define SCAT_Y 64                    // 64*4 blocks * 256 thr = 65536 scatter threads

__device__ __forceinline__ void stage_load(
    uint32_t sbase, int stage,
    const __half* __restrict__ A, const __half* __restrict__ B,
    int m0, int n0, int k0, int tid)
{
    uint32_t s0 = sbase + (uint32_t)stage * STAGE_BYTES;
#pragma unroll
    for (int i = tid; i < 512; i += 256) {
        int r = i >> 2, s = i & 3;
        uint32_t so = (uint32_t)r * ROWB + (uint32_t)s * 16u;
        const char* ga = (const char*)(A + (size_t)(m0 + r) * DIM + k0) + s * 16;
        const char* gb = (const char*)(B + (size_t)(n0 + r) * DIM + k0) + s * 16;
        CP_ASYNC16(s0 + OFF_A + so, ga);
        CP_ASYNC16(s0 + OFF_B + so, gb);
    }
}

__global__ __launch_bounds__(256, 2) void gemm_f16_kernel(
    const __half* __restrict__ A, const __half* __restrict__ B,
    const float* __restrict__ bias, __half* __restrict__ C,
    int extraY,
    const int* __restrict__ esrc, const int* __restrict__ edst,
    const float* __restrict__ eval)
{
    if ((int)blockIdx.y < extraY) {
        // CSR scatter, grid-strided; overlaps with gemm tensor work
        int t0 = blockIdx.y * gridDim.x + blockIdx.x;          // 0..255
        int gtid = t0 * 256 + threadIdx.x;
        const int stride = SCAT_Y * 4 * 256;                   // 65536
        for (int e = gtid; e < N_EDGES; e += stride) {
            int d = __ldcs(edst + e);
            int pos = g_row_ptr[d] + atomicAdd(&g_counts[d], 1);
            g_srcs[pos] = __ldcs(esrc + e);
            g_vals[pos] = __ldcs(eval + e);
        }
        return;
    }

    extern __shared__ char sm[];
    const uint32_t sbase = smem_u32(sm);
    const int tid  = threadIdx.x;
    const int warp = tid >> 5;
    const int lane = tid & 31;
    const int wm = warp & 1;
    const int wn = warp >> 1;
    const int n0 = blockIdx.x * 128;              // n fastest -> wave shares A rows
    const int m0 = (blockIdx.y - extraY) * 128;

    float acc[4][4][4];
#pragma unroll
    for (int a = 0; a < 4; a++)
#pragma unroll
        for (int b = 0; b < 4; b++)
#pragma unroll
            for (int c = 0; c < 4; c++) acc[a][b][c] = 0.f;

    const int a_row = lane & 15;
    const int a_koff = (lane >> 4) * 8;
    const int b_g = lane >> 3;
    const int b_nloc = ((b_g >> 1) << 3) + (lane & 7);
    const int b_koff = (b_g & 1) * 8;

    stage_load(sbase, 0, A, B, m0, n0, 0, tid);
    CP_COMMIT();

    for (int it = 0; it < NIT; ++it) {
        if (it + 1 < NIT) {
            stage_load(sbase, (it + 1) & 1, A, B, m0, n0, (it + 1) * BK, tid);
            CP_COMMIT();
            CP_WAIT(1);
        } else {
            CP_WAIT(0);
        }
        __syncthreads();

        const uint32_t st = sbase + (uint32_t)(it & 1) * STAGE_BYTES;
#pragma unroll
        for (int kk = 0; kk < 2; ++kk) {
            const int k16 = kk * 16;
            uint32_t av[4][4];
#pragma unroll
            for (int mi = 0; mi < 4; ++mi) {
                uint32_t ra = (uint32_t)(wm * 64 + mi * 16 + a_row) * ROWB
                            + (uint32_t)(k16 + a_koff) * 2;
                LDSM4(av[mi][0], av[mi][1], av[mi][2], av[mi][3], st + OFF_A + ra);
            }
            uint32_t bv[2][4];
#pragma unroll
            for (int nb = 0; nb < 2; ++nb) {
                uint32_t rb = (uint32_t)(wn * 32 + nb * 16 + b_nloc) * ROWB
                            + (uint32_t)(k16 + b_koff) * 2;
                LDSM4(bv[nb][0], bv[nb][1], bv[nb][2], bv[nb][3], st + OFF_B + rb);
            }
#pragma unroll
            for (int mi = 0; mi < 4; ++mi) {
#pragma unroll
                for (int j = 0; j < 4; ++j) {
                    const int nb = j >> 1, blk = j & 1;
                    MMA16816F(acc[mi][j], av[mi], bv[nb][blk * 2], bv[nb][blk * 2 + 1]);
                }
            }
        }
        __syncthreads();
    }

    // epilogue: bias add + fp16 store (plain stores -> lands in L2 for SpMM)
#pragma unroll
    for (int mi = 0; mi < 4; ++mi) {
        int row = m0 + wm * 64 + mi * 16 + (lane >> 2);
#pragma unroll
        for (int j = 0; j < 4; ++j) {
            int col = n0 + wn * 32 + j * 8 + (lane & 3) * 2;
            float b0 = bias[col], b1 = bias[col + 1];
            __half2 v0 = __floats2half2_rn(acc[mi][j][0] + b0, acc[mi][j][1] + b1);
            __half2 v1 = __floats2half2_rn(acc[mi][j][2] + b0, acc[mi][j][3] + b1);
            *(__half2*)(C + (size_t)row * DIM + col) = v0;
            *(__half2*)(C + (size_t)(row + 8) * DIM + col) = v1;
        }
    }
}

// ---------------- SpMM (CSR by dst), fp16 gather, one warp per row -----------
struct Acc16 { float2 f[8]; };

__device__ __forceinline__ void gather_row_h(const __half* __restrict__ H,
                                             int beg, int end, int lane, Acc16& A) {
#pragma unroll
    for (int j = 0; j < 8; j++) A.f[j] = make_float2(0.f, 0.f);
    for (int base = beg; base < end; base += 32) {
        int cnt = end - base; if (cnt > 32) cnt = 32;
        int s = 0; float v = 0.f;
        if (lane < cnt) { s = __ldcs(g_srcs + base + lane); v = __ldcs(g_vals + base + lane); }
        for (int k = 0; k < cnt; k++) {
            int   sk = __shfl_sync(0xffffffffu, s, k);
            float vk = __shfl_sync(0xffffffffu, v, k);
            const uint4* hp = (const uint4*)(H + (size_t)sk * DIM);
            uint4 q0 = hp[lane];
            uint4 q1 = hp[lane + 32];
            const __half2* h0 = (const __half2*)&q0;
            const __half2* h1 = (const __half2*)&q1;
#pragma unroll
            for (int j = 0; j < 4; j++) {
                float2 f0 = __half22float2(h0[j]);
                float2 f1 = __half22float2(h1[j]);
                A.f[j].x     = fmaf(vk, f0.x, A.f[j].x);
                A.f[j].y     = fmaf(vk, f0.y, A.f[j].y);
                A.f[j + 4].x = fmaf(vk, f1.x, A.f[j + 4].x);
                A.f[j + 4].y = fmaf(vk, f1.y, A.f[j + 4].y);
            }
        }
    }
#pragma unroll
    for (int j = 0; j < 8; j++) {
        A.f[j].x = fmaxf(A.f[j].x, 0.f);
        A.f[j].y = fmaxf(A.f[j].y, 0.f);
    }
}

// layer-1: gather fp16 -> relu -> fp16 (gemm2 input)
__global__ __launch_bounds__(256) void spmm_h16_kernel(const __half* __restrict__ H,
                                                       __half* __restrict__ outh) {
    int row  = (blockIdx.x * blockDim.x + threadIdx.x) >> 5;
    int lane = threadIdx.x & 31;
    if (row >= N_NODES) return;
    Acc16 A;
    gather_row_h(H, g_row_ptr[row], g_row_ptr[row + 1], lane, A);
    __half* op = outh + (size_t)row * DIM;
#pragma unroll
    for (int half = 0; half < 2; half++) {
        uint4 pk;
        __half2 p0 = __floats2half2_rn(A.f[half * 4 + 0].x, A.f[half * 4 + 0].y);
        __half2 p1 = __floats2half2_rn(A.f[half * 4 + 1].x, A.f[half * 4 + 1].y);
        __half2 p2 = __floats2half2_rn(A.f[half * 4 + 2].x, A.f[half * 4 + 2].y);
        __half2 p3 = __floats2half2_rn(A.f[half * 4 + 3].x, A.f[half * 4 + 3].y);
        pk.x = *(uint32_t*)&p0; pk.y = *(uint32_t*)&p1;
        pk.z = *(uint32_t*)&p2; pk.w = *(uint32_t*)&p3;
        __stcs((uint4*)(op + (lane + half * 32) * 8), pk);
    }
}

// layer-2: gather fp16 -> relu -> fp32 final output
__global__ __launch_bounds__(256) void spmm_out_kernel(const __half* __restrict__ H,
                                                       float* __restrict__ out) {
    int row  = (blockIdx.x * blockDim.x + threadIdx.x) >> 5;
    int lane = threadIdx.x & 31;
    if (row >= N_NODES) return;
    Acc16 A;
    gather_row_h(H, g_row_ptr[row], g_row_ptr[row + 1], lane, A);
    float* op = out + (size_t)row * DIM;
#pragma unroll
    for (int half = 0; half < 2; half++) {
        float* p = op + (lane + half * 32) * 8;
        float4 v0 = make_float4(A.f[half * 4 + 0].x, A.f[half * 4 + 0].y,
                                A.f[half * 4 + 1].x, A.f[half * 4 + 1].y);
        float4 v1 = make_float4(A.f[half * 4 + 2].x, A.f[half * 4 + 2].y,
                                A.f[half * 4 + 3].x, A.f[half * 4 + 3].y);
        __stcs((float4*)p, v0);
        __stcs((float4*)(p + 4), v1);
    }
}

// ---------------- launcher ----------------------------------------------------
extern "C" void kernel_launch(void* const* d_in, const int* in_sizes, int n_in,
                              void* d_out, int out_size)
{
    const float* x    = (const float*)d_in[0];
    const int*   asrc = (const int*)  d_in[1];
    const int*   adst = (const int*)  d_in[2];
    const float* aval = (const float*)d_in[3];
    const float* W1   = (const float*)d_in[4];
    const float* b1   = (const float*)d_in[5];
    const float* W2   = (const float*)d_in[6];
    const float* b2   = (const float*)d_in[7];
    float* out = (float*)d_out;

    __half *x16, *o16, *h16, *w1t, *w2t;
    cudaGetSymbolAddress((void**)&x16, g_x16);
    cudaGetSymbolAddress((void**)&o16, g_o16);
    cudaGetSymbolAddress((void**)&h16, g_h16);
    cudaGetSymbolAddress((void**)&w1t, g_w1t);
    cudaGetSymbolAddress((void**)&w2t, g_w2t);

    cudaFuncSetAttribute(gemm_f16_kernel, cudaFuncAttributeMaxDynamicSharedMemorySize,
                         GEMM_SMEM);

    // 1) zero degree counters (must precede hist)
    zero_counts_kernel<<<(N_NODES + 255) / 256, 256>>>();
    // 2) merged prep: x->fp16 || degree histogram || W1/W2 transpose->fp16
    prep_kernel<<<NB_PREP, 256>>>(x, adst, W1, W2);
    // 3) prefix-sum -> row_ptr (counts reset for scatter)
    scan_kernel<<<1, 1024>>>();
    // 4) gemm1 with leading scatter blocks (profiled slot idx 3)
    dim3 g1(DIM / 128, SCAT_Y + M_PAD / 128);
    gemm_f16_kernel<<<g1, 256, GEMM_SMEM>>>(x16, w1t, b1, o16, SCAT_Y, asrc, adst, aval);
    // 5) layer-1 aggregate: fp16 gather -> fp16 h1
    spmm_h16_kernel<<<(N_NODES + 7) / 8, 256>>>(o16, h16);
    // 6) gemm2 (no scatter blocks)
    dim3 g2(DIM / 128, M_PAD / 128);
    gemm_f16_kernel<<<g2, 256, GEMM_SMEM>>>(h16, w2t, b2, o16, 0, nullptr, nullptr, nullptr);
    // 7) layer-2 aggregate -> fp32 out
    spmm_out_kernel<<<(N_NODES + 7) / 8, 256>>>(o16, out);
}

// round 11
// speedup vs baseline: 2.1743x; 1.0194x over previous
#include <cuda_runtime.h>
#include <cuda_fp16.h>
#include <cstdint>
#include <cstddef>

#define N_NODES 100000
#define M_PAD   100096            // 782 * 128
#define N_EDGES 3200000
#define DIM 512

// ---------------- scratch (device globals; no runtime allocation) ----------
__device__ __half g_x16[(size_t)M_PAD * DIM];    // fp16(x)
__device__ __half g_o16[(size_t)M_PAD * DIM];    // gemm outputs (both layers)
__device__ __half g_h16[(size_t)M_PAD * DIM];    // spmm1 output (gemm2 input)
__device__ __half g_w1t[DIM * DIM];
__device__ __half g_w2t[DIM * DIM];
__device__ int   g_row_ptr[N_NODES + 1];
__device__ int   g_counts[N_NODES];
__device__ int   g_srcs[N_EDGES];
__device__ float g_vals[N_EDGES];

// ---------------- PTX helpers ----------------------------------------------
__device__ __forceinline__ uint32_t smem_u32(const void* p) {
    uint32_t a;
    asm("{ .reg .u64 t; cvta.to.shared.u64 t, %1; cvt.u32.u64 %0, t; }" : "=r"(a) : "l"(p));
    return a;
}

#define CP_ASYNC16(smaddr, gptr) \
    asm volatile("cp.async.cg.shared.global [%0], [%1], 16;" :: "r"(smaddr), "l"(gptr))
#define CP_COMMIT() asm volatile("cp.async.commit_group;" ::: "memory")
#define CP_WAIT(N)  asm volatile("cp.async.wait_group %0;" :: "n"(N) : "memory")

#define LDSM4(R0, R1, R2, R3, addr) \
    asm volatile("ldmatrix.sync.aligned.m8n8.x4.shared.b16 {%0,%1,%2,%3}, [%4];" \
                 : "=r"(R0), "=r"(R1), "=r"(R2), "=r"(R3) : "r"(addr))

#define MMA16816F(C, A, B0, B1) \
    asm volatile("mma.sync.aligned.m16n8k16.row.col.f32.f16.f16.f32 " \
                 "{%0,%1,%2,%3}, {%4,%5,%6,%7}, {%8,%9}, {%0,%1,%2,%3};" \
                 : "+f"((C)[0]), "+f"((C)[1]), "+f"((C)[2]), "+f"((C)[3]) \
                 : "r"((A)[0]), "r"((A)[1]), "r"((A)[2]), "r"((A)[3]), \
                   "r"(B0), "r"(B1))

// ---------------- CSR pieces ------------------------------------------------
__global__ void zero_counts_kernel() {
    int i = blockIdx.x * blockDim.x + threadIdx.x;
    if (i < N_NODES) g_counts[i] = 0;
}

__global__ __launch_bounds__(1024) void scan_kernel() {
    __shared__ int partials[1024];
    int tid = threadIdx.x;
    const int CHUNK = (N_NODES + 1023) / 1024;
    int b = tid * CHUNK;
    int e = b + CHUNK; if (e > N_NODES) e = N_NODES;
    if (b > N_NODES) b = N_NODES;
    int sum = 0;
    for (int i = b; i < e; i++) sum += g_counts[i];
    partials[tid] = sum;
    __syncthreads();
    for (int off = 1; off < 1024; off <<= 1) {
        int t = (tid >= off) ? partials[tid - off] : 0;
        __syncthreads();
        partials[tid] += t;
        __syncthreads();
    }
    int run = partials[tid] - sum;
    for (int i = b; i < e; i++) {
        g_row_ptr[i] = run;
        run += g_counts[i];
        g_counts[i] = 0;
    }
    if (tid == 1023) g_row_ptr[N_NODES] = partials[1023];
}

// ---------------- merged prep: convert_x || hist || W transposes -------------
#define NB_CONV 12512     // 12512 blocks * 1024 float4 = M_PAD*DIM/4
#define NB_HIST 1568
#define NB_W    1024      // 1024 blocks * 256 = DIM*DIM
#define NB_PREP (NB_CONV + NB_HIST + 2 * NB_W)

__global__ __launch_bounds__(256) void prep_kernel(
    const float* __restrict__ x, const int* __restrict__ dst,
    const float* __restrict__ W1, const float* __restrict__ W2)
{
    int b = blockIdx.x;
    if (b < NB_CONV) {
#pragma unroll
        for (int j = 0; j < 4; j++) {
            size_t i = (size_t)b * 1024 + j * 256 + threadIdx.x;
            size_t row = i / (DIM / 4);
            float4 v = make_float4(0.f, 0.f, 0.f, 0.f);
            if (row < N_NODES) v = ((const float4*)x)[i];
            __half2 h0 = __floats2half2_rn(v.x, v.y);
            __half2 h1 = __floats2half2_rn(v.z, v.w);
            uint2 pk;
            pk.x = *(uint32_t*)&h0;
            pk.y = *(uint32_t*)&h1;
            ((uint2*)g_x16)[i] = pk;
        }
    } else if (b < NB_CONV + NB_HIST) {
        int gtid = (b - NB_CONV) * 256 + threadIdx.x;
        const int stride = NB_HIST * 256;
        for (int e = gtid; e < N_EDGES; e += stride)
            atomicAdd(&g_counts[__ldcs(dst + e)], 1);
    } else {
        int b3 = b - NB_CONV - NB_HIST;
        const float* W = (b3 < NB_W) ? W1 : W2;
        __half* Wt = (b3 < NB_W) ? g_w1t : g_w2t;
        int idx = (b3 & (NB_W - 1)) * 256 + threadIdx.x;
        int k = idx >> 9, n = idx & 511;
        Wt[n * DIM + k] = __float2half_rn(W[idx]);
    }
}

// ---------------- HMMA fp16 GEMM, 3-stage single-sync pipeline ---------------
// C[.,512](fp16) = A(fp16) @ Wt^T + bias, fp32 accum.
// CTA 128x128, 8 warps (warp 64x32), K-chunk 32, 3-stage cp.async pipeline.
// Leading extraY block-rows perform the CSR scatter (gemm1 only).
#define BK 32
#define ROWB 80
#define OFF_A   0
#define OFF_B   10240
#define STAGE_BYTES 20480
#define NSTAGE 3
#define GEMM_SMEM (NSTAGE * STAGE_BYTES)
#define NIT (DIM / BK)               // 16
#define SCAT_Y 64                    // 64*4 blocks * 256 thr = 65536 scatter threads

__device__ __forceinline__ void stage_load(
    uint32_t sbase, int stage,
    const __half* __restrict__ A, const __half* __restrict__ B,
    int m0, int n0, int k0, int tid)
{
    uint32_t s0 = sbase + (uint32_t)stage * STAGE_BYTES;
#pragma unroll
    for (int i = tid; i < 512; i += 256) {
        int r = i >> 2, s = i & 3;
        uint32_t so = (uint32_t)r * ROWB + (uint32_t)s * 16u;
        const char* ga = (const char*)(A + (size_t)(m0 + r) * DIM + k0) + s * 16;
        const char* gb = (const char*)(B + (size_t)(n0 + r) * DIM + k0) + s * 16;
        CP_ASYNC16(s0 + OFF_A + so, ga);
        CP_ASYNC16(s0 + OFF_B + so, gb);
    }
}

__global__ __launch_bounds__(256, 2) void gemm_f16_kernel(
    const __half* __restrict__ A, const __half* __restrict__ B,
    const float* __restrict__ bias, __half* __restrict__ C,
    int extraY,
    const int* __restrict__ esrc, const int* __restrict__ edst,
    const float* __restrict__ eval)
{
    if ((int)blockIdx.y < extraY) {
        // CSR scatter, grid-strided; overlaps with gemm tensor work
        int t0 = blockIdx.y * gridDim.x + blockIdx.x;          // 0..255
        int gtid = t0 * 256 + threadIdx.x;
        const int stride = SCAT_Y * 4 * 256;                   // 65536
        for (int e = gtid; e < N_EDGES; e += stride) {
            int d = __ldcs(edst + e);
            int pos = g_row_ptr[d] + atomicAdd(&g_counts[d], 1);
            g_srcs[pos] = __ldcs(esrc + e);
            g_vals[pos] = __ldcs(eval + e);
        }
        return;
    }

    extern __shared__ char sm[];
    const uint32_t sbase = smem_u32(sm);
    const int tid  = threadIdx.x;
    const int warp = tid >> 5;
    const int lane = tid & 31;
    const int wm = warp & 1;
    const int wn = warp >> 1;
    const int n0 = blockIdx.x * 128;              // n fastest -> wave shares A rows
    const int m0 = (blockIdx.y - extraY) * 128;

    float acc[4][4][4];
#pragma unroll
    for (int a = 0; a < 4; a++)
#pragma unroll
        for (int b = 0; b < 4; b++)
#pragma unroll
            for (int c = 0; c < 4; c++) acc[a][b][c] = 0.f;

    const int a_row = lane & 15;
    const int a_koff = (lane >> 4) * 8;
    const int b_g = lane >> 3;
    const int b_nloc = ((b_g >> 1) << 3) + (lane & 7);
    const int b_koff = (b_g & 1) * 8;

    // prime stages 0 and 1
    stage_load(sbase, 0, A, B, m0, n0, 0, tid);
    CP_COMMIT();
    stage_load(sbase, 1, A, B, m0, n0, BK, tid);
    CP_COMMIT();

    int stg = 0;                  // stage index of iteration `it` (mod NSTAGE)
    for (int it = 0; it < NIT; ++it) {
        if (it + 1 < NIT) { CP_WAIT(1); } else { CP_WAIT(0); }
        __syncthreads();          // stage `stg` ready; all warps done with stage (stg+2)%3

        if (it + 2 < NIT) {
            int nstg = stg + 2; if (nstg >= NSTAGE) nstg -= NSTAGE;
            stage_load(sbase, nstg, A, B, m0, n0, (it + 2) * BK, tid);
            CP_COMMIT();
        }

        const uint32_t st = sbase + (uint32_t)stg * STAGE_BYTES;
#pragma unroll
        for (int kk = 0; kk < 2; ++kk) {
            const int k16 = kk * 16;
            uint32_t av[4][4];
#pragma unroll
            for (int mi = 0; mi < 4; ++mi) {
                uint32_t ra = (uint32_t)(wm * 64 + mi * 16 + a_row) * ROWB
                            + (uint32_t)(k16 + a_koff) * 2;
                LDSM4(av[mi][0], av[mi][1], av[mi][2], av[mi][3], st + OFF_A + ra);
            }
            uint32_t bv[2][4];
#pragma unroll
            for (int nb = 0; nb < 2; ++nb) {
                uint32_t rb = (uint32_t)(wn * 32 + nb * 16 + b_nloc) * ROWB
                            + (uint32_t)(k16 + b_koff) * 2;
                LDSM4(bv[nb][0], bv[nb][1], bv[nb][2], bv[nb][3], st + OFF_B + rb);
            }
#pragma unroll
            for (int mi = 0; mi < 4; ++mi) {
#pragma unroll
                for (int j = 0; j < 4; ++j) {
                    const int nb = j >> 1, blk = j & 1;
                    MMA16816F(acc[mi][j], av[mi], bv[nb][blk * 2], bv[nb][blk * 2 + 1]);
                }
            }
        }
        if (++stg >= NSTAGE) stg = 0;
    }

    // epilogue: bias add + fp16 store (plain stores -> lands in L2 for SpMM)
#pragma unroll
    for (int mi = 0; mi < 4; ++mi) {
        int row = m0 + wm * 64 + mi * 16 + (lane >> 2);
#pragma unroll
        for (int j = 0; j < 4; ++j) {
            int col = n0 + wn * 32 + j * 8 + (lane & 3) * 2;
            float b0 = bias[col], b1 = bias[col + 1];
            __half2 v0 = __floats2half2_rn(acc[mi][j][0] + b0, acc[mi][j][1] + b1);
            __half2 v1 = __floats2half2_rn(acc[mi][j][2] + b0, acc[mi][j][3] + b1);
            *(__half2*)(C + (size_t)row * DIM + col) = v0;
            *(__half2*)(C + (size_t)(row + 8) * DIM + col) = v1;
        }
    }
}

// ---------------- SpMM (CSR by dst), fp16 gather, one warp per row -----------
struct Acc16 { float2 f[8]; };

__device__ __forceinline__ void gather_row_h(const __half* __restrict__ H,
                                             int beg, int end, int lane, Acc16& A) {
#pragma unroll
    for (int j = 0; j < 8; j++) A.f[j] = make_float2(0.f, 0.f);
    for (int base = beg; base < end; base += 32) {
        int cnt = end - base; if (cnt > 32) cnt = 32;
        int s = 0; float v = 0.f;
        if (lane < cnt) { s = __ldcs(g_srcs + base + lane); v = __ldcs(g_vals + base + lane); }
        for (int k = 0; k < cnt; k++) {
            int   sk = __shfl_sync(0xffffffffu, s, k);
            float vk = __shfl_sync(0xffffffffu, v, k);
            const uint4* hp = (const uint4*)(H + (size_t)sk * DIM);
            uint4 q0 = hp[lane];
            uint4 q1 = hp[lane + 32];
            const __half2* h0 = (const __half2*)&q0;
            const __half2* h1 = (const __half2*)&q1;
#pragma unroll
            for (int j = 0; j < 4; j++) {
                float2 f0 = __half22float2(h0[j]);
                float2 f1 = __half22float2(h1[j]);
                A.f[j].x     = fmaf(vk, f0.x, A.f[j].x);
                A.f[j].y     = fmaf(vk, f0.y, A.f[j].y);
                A.f[j + 4].x = fmaf(vk, f1.x, A.f[j + 4].x);
                A.f[j + 4].y = fmaf(vk, f1.y, A.f[j + 4].y);
            }
        }
    }
#pragma unroll
    for (int j = 0; j < 8; j++) {
        A.f[j].x = fmaxf(A.f[j].x, 0.f);
        A.f[j].y = fmaxf(A.f[j].y, 0.f);
    }
}

// layer-1: gather fp16 -> relu -> fp16 (gemm2 input)
__global__ __launch_bounds__(256) void spmm_h16_kernel(const __half* __restrict__ H,
                                                       __half* __restrict__ outh) {
    int row  = (blockIdx.x * blockDim.x + threadIdx.x) >> 5;
    int lane = threadIdx.x & 31;
    if (row >= N_NODES) return;
    Acc16 A;
    gather_row_h(H, g_row_ptr[row], g_row_ptr[row + 1], lane, A);
    __half* op = outh + (size_t)row * DIM;
#pragma unroll
    for (int half = 0; half < 2; half++) {
        uint4 pk;
        __half2 p0 = __floats2half2_rn(A.f[half * 4 + 0].x, A.f[half * 4 + 0].y);
        __half2 p1 = __floats2half2_rn(A.f[half * 4 + 1].x, A.f[half * 4 + 1].y);
        __half2 p2 = __floats2half2_rn(A.f[half * 4 + 2].x, A.f[half * 4 + 2].y);
        __half2 p3 = __floats2half2_rn(A.f[half * 4 + 3].x, A.f[half * 4 + 3].y);
        pk.x = *(uint32_t*)&p0; pk.y = *(uint32_t*)&p1;
        pk.z = *(uint32_t*)&p2; pk.w = *(uint32_t*)&p3;
        __stcs((uint4*)(op + (lane + half * 32) * 8), pk);
    }
}

// layer-2: gather fp16 -> relu -> fp32 final output
__global__ __launch_bounds__(256) void spmm_out_kernel(const __half* __restrict__ H,
                                                       float* __restrict__ out) {
    int row  = (blockIdx.x * blockDim.x + threadIdx.x) >> 5;
    int lane = threadIdx.x & 31;
    if (row >= N_NODES) return;
    Acc16 A;
    gather_row_h(H, g_row_ptr[row], g_row_ptr[row + 1], lane, A);
    float* op = out + (size_t)row * DIM;
#pragma unroll
    for (int half = 0; half < 2; half++) {
        float* p = op + (lane + half * 32) * 8;
        float4 v0 = make_float4(A.f[half * 4 + 0].x, A.f[half * 4 + 0].y,
                                A.f[half * 4 + 1].x, A.f[half * 4 + 1].y);
        float4 v1 = make_float4(A.f[half * 4 + 2].x, A.f[half * 4 + 2].y,
                                A.f[half * 4 + 3].x, A.f[half * 4 + 3].y);
        __stcs((float4*)p, v0);
        __stcs((float4*)(p + 4), v1);
    }
}

// ---------------- launcher ----------------------------------------------------
extern "C" void kernel_launch(void* const* d_in, const int* in_sizes, int n_in,
                              void* d_out, int out_size)
{
    const float* x    = (const float*)d_in[0];
    const int*   asrc = (const int*)  d_in[1];
    const int*   adst = (const int*)  d_in[2];
    const float* aval = (const float*)d_in[3];
    const float* W1   = (const float*)d_in[4];
    const float* b1   = (const float*)d_in[5];
    const float* W2   = (const float*)d_in[6];
    const float* b2   = (const float*)d_in[7];
    float* out = (float*)d_out;

    __half *x16, *o16, *h16, *w1t, *w2t;
    cudaGetSymbolAddress((void**)&x16, g_x16);
    cudaGetSymbolAddress((void**)&o16, g_o16);
    cudaGetSymbolAddress((void**)&h16, g_h16);
    cudaGetSymbolAddress((void**)&w1t, g_w1t);
    cudaGetSymbolAddress((void**)&w2t, g_w2t);

    cudaFuncSetAttribute(gemm_f16_kernel, cudaFuncAttributeMaxDynamicSharedMemorySize,
                         GEMM_SMEM);

    // 1) zero degree counters (must precede hist)
    zero_counts_kernel<<<(N_NODES + 255) / 256, 256>>>();
    // 2) merged prep: x->fp16 || degree histogram || W1/W2 transpose->fp16
    prep_kernel<<<NB_PREP, 256>>>(x, adst, W1, W2);
    // 3) prefix-sum -> row_ptr (counts reset for scatter)
    scan_kernel<<<1, 1024>>>();
    // 4) gemm1 with leading scatter blocks (profiled slot idx 3)
    dim3 g1(DIM / 128, SCAT_Y + M_PAD / 128);
    gemm_f16_kernel<<<g1, 256, GEMM_SMEM>>>(x16, w1t, b1, o16, SCAT_Y, asrc, adst, aval);
    // 5) layer-1 aggregate: fp16 gather -> fp16 h1
    spmm_h16_kernel<<<(N_NODES + 7) / 8, 256>>>(o16, h16);
    // 6) gemm2 (no scatter blocks)
    dim3 g2(DIM / 128, M_PAD / 128);
    gemm_f16_kernel<<<g2, 256, GEMM_SMEM>>>(h16, w2t, b2, o16, 0, nullptr, nullptr, nullptr);
    // 7) layer-2 aggregate -> fp32 out
    spmm_out_kernel<<<(N_NODES + 7) / 8, 256>>>(o16, out);
}